// round 4
// baseline (speedup 1.0000x reference)
#include <cuda_runtime.h>
#include <math.h>

typedef unsigned long long u64;

#define MSG_DIM 100
#define MEM_DIM 172
#define KDIM    272          // MSG_DIM + MEM_DIM
#define JPAD    176          // MEM_DIM padded
#define ROWS    16           // rows (update entries) per gru block
#define NTHREADS 192
#define XSTRIDE 20           // smem row stride (floats)
#define MASK_CAP (4u << 20)

// ---------------------------------------------------------------------------
// Persistent scratch: repacked weights + bias + updated-node mask.
// ---------------------------------------------------------------------------
__device__ float g_Wr [KDIM   * JPAD];
__device__ float g_Wz [KDIM   * JPAD];
__device__ float g_Wni[MSG_DIM * JPAD];
__device__ float g_Wnh[MEM_DIM * JPAD];
__device__ float g_bias[4 * JPAD];
__device__ unsigned char g_mask[MASK_CAP];

// ---- packed fp32x2 helpers ------------------------------------------------
__device__ __forceinline__ u64 fma2(u64 b, u64 x, u64 c) {
    u64 d;
    asm("fma.rn.f32x2 %0, %1, %2, %3;" : "=l"(d) : "l"(b), "l"(x), "l"(c));
    return d;
}
__device__ __forceinline__ u64 dup2(float v) {
    u64 d; unsigned u = __float_as_uint(v);
    asm("mov.b64 %0, {%1, %1};" : "=l"(d) : "r"(u));
    return d;
}
__device__ __forceinline__ float2 unpack2(u64 d) {
    unsigned lo, hi;
    asm("mov.b64 {%0, %1}, %2;" : "=r"(lo), "=r"(hi) : "l"(d));
    return make_float2(__uint_as_float(lo), __uint_as_float(hi));
}

// ---------------------------------------------------------------------------
// Prep: repack W_ih [516,100], W_hh [516,172] into K-major planes + bias.
// ---------------------------------------------------------------------------
__global__ void prep_kernel(const float* __restrict__ W_ih,
                            const float* __restrict__ W_hh,
                            const float* __restrict__ b_ih,
                            const float* __restrict__ b_hh) {
    int idx = blockIdx.x * blockDim.x + threadIdx.x;
    if (idx < KDIM * JPAD) {
        int k = idx / JPAD;
        int j = idx - k * JPAD;
        float wr = 0.f, wz = 0.f;
        if (j < MEM_DIM) {
            if (k < MSG_DIM) {
                wr = W_ih[j * MSG_DIM + k];
                wz = W_ih[(MEM_DIM + j) * MSG_DIM + k];
            } else {
                int kk = k - MSG_DIM;
                wr = W_hh[j * MEM_DIM + kk];
                wz = W_hh[(MEM_DIM + j) * MEM_DIM + kk];
            }
        }
        g_Wr[k * JPAD + j] = wr;
        g_Wz[k * JPAD + j] = wz;
        if (k < MSG_DIM)
            g_Wni[k * JPAD + j] = (j < MEM_DIM) ? W_ih[(2 * MEM_DIM + j) * MSG_DIM + k] : 0.f;
        if (k < MEM_DIM)
            g_Wnh[k * JPAD + j] = (j < MEM_DIM) ? W_hh[(2 * MEM_DIM + j) * MEM_DIM + k] : 0.f;
    }
    if (idx < JPAD) {
        int j = idx;
        float br = 0.f, bz = 0.f, bi = 0.f, bh = 0.f;
        if (j < MEM_DIM) {
            br = b_ih[j]               + b_hh[j];
            bz = b_ih[MEM_DIM + j]     + b_hh[MEM_DIM + j];
            bi = b_ih[2 * MEM_DIM + j];
            bh = b_hh[2 * MEM_DIM + j];
        }
        g_bias[j]            = br;
        g_bias[JPAD + j]     = bz;
        g_bias[2 * JPAD + j] = bi;
        g_bias[3 * JPAD + j] = bh;
    }
}

__global__ void mask_kernel(const int* __restrict__ node_ids, int n_upd) {
    int i = blockIdx.x * blockDim.x + threadIdx.x;
    if (i < n_upd) {
        int nid = node_ids[i];
        if (nid >= 0 && (unsigned)nid < MASK_CAP) g_mask[nid] = 1;
    }
}

// Fallback plain copy (non-merged path)
__global__ void copy_kernel(const float* __restrict__ src, float* __restrict__ dst, long long n) {
    long long i = (long long)blockIdx.x * blockDim.x + threadIdx.x;
    long long n4 = n >> 2;
    if (i < n4) ((float4*)dst)[i] = ((const float4*)src)[i];
    long long tail = n & 3;
    if (i < tail) dst[n4 * 4 + i] = src[n4 * 4 + i];
}

// ---------------------------------------------------------------------------
// Fused kernel. bid < gru_blocks -> GRU role (round-1 code, verbatim).
// Then copy4 role (one float4/thread, mask-guarded), then last_update role.
// Copy CTAs backfill SM slots while GRU CTAs run (tiny reg/smem footprint).
// ---------------------------------------------------------------------------
__global__ void __launch_bounds__(NTHREADS)
fused_kernel(const int*   __restrict__ node_ids,
             const float* __restrict__ messages,
             const float* __restrict__ timestamps,
             const float* __restrict__ memory,
             const float* __restrict__ last_update,
             float*       __restrict__ out,
             int n_upd, long long n_nodes,
             int gru_blocks, int copy4_blocks)
{
    const int tid = threadIdx.x;
    const int bid = blockIdx.x;

    if (bid >= gru_blocks) {
        const unsigned nmem = (unsigned)(n_nodes * (long long)MEM_DIM);
        if (bid - gru_blocks < copy4_blocks) {
            // ---- memory passthrough: one float4 per thread ----
            unsigned i = (unsigned)(bid - gru_blocks) * NTHREADS + tid;
            if (i < (nmem >> 2)) {
                unsigned row = (i * 4u) / MEM_DIM;
                if (!g_mask[row])
                    ((float4*)out)[i] = ((const float4*)memory)[i];
            }
        } else {
            // ---- last_update passthrough: one float per thread ----
            unsigned i = (unsigned)(bid - gru_blocks - copy4_blocks) * NTHREADS + tid;
            if (i < (unsigned)n_nodes) {
                if (!g_mask[i])
                    out[nmem + i] = last_update[i];
            }
        }
        return;
    }

    // ---------------- GRU role (round-1 kernel) ----------------
    __shared__ __align__(16) float xT[KDIM][XSTRIDE];   // transposed [k][row]
    __shared__ int   s_nid[ROWS];
    __shared__ float s_ts [ROWS];

    const int row0 = bid * ROWS;

    if (tid < ROWS) {
        int r = row0 + tid;
        if (r < n_upd) { s_nid[tid] = node_ids[r]; s_ts[tid] = timestamps[r]; }
        else           { s_nid[tid] = -1;          s_ts[tid] = 0.f; }
    }
    __syncthreads();

    for (int idx = tid; idx < ROWS * KDIM; idx += NTHREADS) {
        int r = idx / KDIM;
        int k = idx - r * KDIM;
        float v = 0.f;
        int nid = s_nid[r];
        if (nid >= 0) {
            v = (k < MSG_DIM)
              ? messages[(size_t)(row0 + r) * MSG_DIM + k]
              : memory  [(size_t)nid * MEM_DIM + (k - MSG_DIM)];
        }
        xT[k][r] = v;
    }
    __syncthreads();

    const int j = tid;
    if (j < MEM_DIM) {
        u64 ar2[ROWS / 2], az2[ROWS / 2], ani2[ROWS / 2], anh2[ROWS / 2];
        u64 z0 = dup2(0.f);
        #pragma unroll
        for (int p = 0; p < ROWS / 2; p++) { ar2[p] = z0; az2[p] = z0; ani2[p] = z0; anh2[p] = z0; }

        const float* __restrict__ pr = g_Wr  + j;
        const float* __restrict__ pz = g_Wz  + j;
        const float* __restrict__ pi = g_Wni + j;
        const float* __restrict__ ph = g_Wnh + j;

        // Phase 1: k in [0,100) -> gates r, z, i_n
        #pragma unroll 2
        for (int k = 0; k < MSG_DIM; k++) {
            u64 wr2 = dup2(pr[k * JPAD]);
            u64 wz2 = dup2(pz[k * JPAD]);
            u64 wi2 = dup2(pi[k * JPAD]);
            const ulonglong2* xq = (const ulonglong2*)&xT[k][0];
            #pragma unroll
            for (int q = 0; q < 4; q++) {
                ulonglong2 xv = xq[q];
                ar2 [2*q]   = fma2(wr2, xv.x, ar2 [2*q]);
                ar2 [2*q+1] = fma2(wr2, xv.y, ar2 [2*q+1]);
                az2 [2*q]   = fma2(wz2, xv.x, az2 [2*q]);
                az2 [2*q+1] = fma2(wz2, xv.y, az2 [2*q+1]);
                ani2[2*q]   = fma2(wi2, xv.x, ani2[2*q]);
                ani2[2*q+1] = fma2(wi2, xv.y, ani2[2*q+1]);
            }
        }
        // Phase 2: k in [100,272) -> gates r, z, h_n
        #pragma unroll 2
        for (int k = MSG_DIM; k < KDIM; k++) {
            u64 wr2 = dup2(pr[k * JPAD]);
            u64 wz2 = dup2(pz[k * JPAD]);
            u64 wh2 = dup2(ph[(k - MSG_DIM) * JPAD]);
            const ulonglong2* xq = (const ulonglong2*)&xT[k][0];
            #pragma unroll
            for (int q = 0; q < 4; q++) {
                ulonglong2 xv = xq[q];
                ar2 [2*q]   = fma2(wr2, xv.x, ar2 [2*q]);
                ar2 [2*q+1] = fma2(wr2, xv.y, ar2 [2*q+1]);
                az2 [2*q]   = fma2(wz2, xv.x, az2 [2*q]);
                az2 [2*q+1] = fma2(wz2, xv.y, az2 [2*q+1]);
                anh2[2*q]   = fma2(wh2, xv.x, anh2[2*q]);
                anh2[2*q+1] = fma2(wh2, xv.y, anh2[2*q+1]);
            }
        }

        const float br = g_bias[j];
        const float bz = g_bias[JPAD + j];
        const float bi = g_bias[2 * JPAD + j];
        const float bh = g_bias[3 * JPAD + j];

        #pragma unroll
        for (int p = 0; p < ROWS / 2; p++) {
            float2 arv = unpack2(ar2[p]);
            float2 azv = unpack2(az2[p]);
            float2 aiv = unpack2(ani2[p]);
            float2 ahv = unpack2(anh2[p]);
            #pragma unroll
            for (int s = 0; s < 2; s++) {
                int r = 2 * p + s;
                int nid = s_nid[r];
                if (nid < 0) continue;
                float a_r = (s ? arv.y : arv.x) + br;
                float a_z = (s ? azv.y : azv.x) + bz;
                float a_i = (s ? aiv.y : aiv.x) + bi;
                float a_h = (s ? ahv.y : ahv.x) + bh;
                float rg = 1.f / (1.f + expf(-a_r));
                float zg = 1.f / (1.f + expf(-a_z));
                float ng = tanhf(a_i + rg * a_h);
                float h_old = xT[MSG_DIM + j][r];
                out[(size_t)nid * MEM_DIM + j] = (1.f - zg) * ng + zg * h_old;
            }
        }
    }

    if (tid < ROWS && s_nid[tid] >= 0) {
        out[(size_t)n_nodes * MEM_DIM + s_nid[tid]] = s_ts[tid];
    }
}

// ---------------------------------------------------------------------------
extern "C" void kernel_launch(void* const* d_in, const int* in_sizes, int n_in,
                              void* d_out, int out_size) {
    const int*   node_ids    = (const int*)  d_in[0];
    const float* messages    = (const float*)d_in[1];
    const float* timestamps  = (const float*)d_in[2];
    const float* memory      = (const float*)d_in[3];
    const float* last_update = (const float*)d_in[4];
    const float* W_ih        = (const float*)d_in[5];
    const float* W_hh        = (const float*)d_in[6];
    const float* b_ih        = (const float*)d_in[7];
    const float* b_hh        = (const float*)d_in[8];
    float* out = (float*)d_out;

    const int       n_upd   = in_sizes[0];
    const long long n_nodes = in_sizes[4];
    const long long nmem    = n_nodes * (long long)MEM_DIM;

    prep_kernel<<<(KDIM * JPAD + 255) / 256, 256>>>(W_ih, W_hh, b_ih, b_hh);

    int gru_blocks = (n_upd + ROWS - 1) / ROWS;
    bool merged = (n_nodes <= (long long)MASK_CAP) && (nmem < (1LL << 31)) &&
                  (n_upd > 0);

    if (merged) {
        mask_kernel<<<(n_upd + 255) / 256, 256>>>(node_ids, n_upd);
        int copy4_blocks = (int)(((nmem >> 2) + NTHREADS - 1) / NTHREADS);
        int lu_blocks    = (int)((n_nodes + NTHREADS - 1) / NTHREADS);
        fused_kernel<<<gru_blocks + copy4_blocks + lu_blocks, NTHREADS>>>(
            node_ids, messages, timestamps, memory, last_update, out,
            n_upd, n_nodes, gru_blocks, copy4_blocks);
    } else {
        long long n4 = (nmem + 3) >> 2;
        copy_kernel<<<(unsigned)((n4 + 255) / 256), 256>>>(memory, out, nmem);
        long long n4b = (n_nodes + 3) >> 2;
        copy_kernel<<<(unsigned)((n4b + 255) / 256), 256>>>(last_update, out + nmem, n_nodes);
        if (n_upd > 0) {
            fused_kernel<<<gru_blocks, NTHREADS>>>(
                node_ids, messages, timestamps, memory, last_update, out,
                n_upd, n_nodes, gru_blocks, 0);
        }
    }
}

// round 5
// speedup vs baseline: 1.8696x; 1.8696x over previous
#include <cuda_runtime.h>
#include <math.h>

typedef unsigned long long u64;

#define MSG_DIM 100
#define MEM_DIM 172
#define KDIM    272          // MSG_DIM + MEM_DIM
#define JPAD    176          // MEM_DIM padded
#define ROWS    16           // rows (update entries) per block
#define NTHREADS 192
#define XSTRIDE 20           // smem row stride (floats), 16B-aligned

// ---------------------------------------------------------------------------
// Persistent scratch: weights repacked K-major into 4 gate planes (+ bias).
// ~574 KB total -> L2 resident, fully coalesced reads in the main loop.
// ---------------------------------------------------------------------------
__device__ float g_Wr [KDIM   * JPAD];   // r-gate, combined W_ih(k<100) | W_hh(k>=100)
__device__ float g_Wz [KDIM   * JPAD];   // z-gate, combined
__device__ float g_Wni[MSG_DIM * JPAD];  // i_n plane  (k < 100)
__device__ float g_Wnh[MEM_DIM * JPAD];  // h_n plane  (k' = k-100)
__device__ float g_bias[4 * JPAD];       // br, bz, bin, bhn

// ---- packed fp32x2 helpers (Blackwell f32x2 pipe: 2x FFMA throughput) -----
__device__ __forceinline__ u64 fma2(u64 b, u64 x, u64 c) {
    u64 d;
    asm("fma.rn.f32x2 %0, %1, %2, %3;" : "=l"(d) : "l"(b), "l"(x), "l"(c));
    return d;
}
__device__ __forceinline__ u64 dup2(float v) {
    u64 d; unsigned u = __float_as_uint(v);
    asm("mov.b64 %0, {%1, %1};" : "=l"(d) : "r"(u));
    return d;
}
__device__ __forceinline__ float2 unpack2(u64 d) {
    unsigned lo, hi;
    asm("mov.b64 {%0, %1}, %2;" : "=r"(lo), "=r"(hi) : "l"(d));
    return make_float2(__uint_as_float(lo), __uint_as_float(hi));
}

// ---------------------------------------------------------------------------
// Prep: repack W_ih [516,100], W_hh [516,172] into K-major planes + bias.
// ---------------------------------------------------------------------------
__global__ void prep_kernel(const float* __restrict__ W_ih,
                            const float* __restrict__ W_hh,
                            const float* __restrict__ b_ih,
                            const float* __restrict__ b_hh) {
    int idx = blockIdx.x * blockDim.x + threadIdx.x;
    if (idx < KDIM * JPAD) {
        int k = idx / JPAD;
        int j = idx - k * JPAD;
        float wr = 0.f, wz = 0.f;
        if (j < MEM_DIM) {
            if (k < MSG_DIM) {
                wr = W_ih[j * MSG_DIM + k];
                wz = W_ih[(MEM_DIM + j) * MSG_DIM + k];
            } else {
                int kk = k - MSG_DIM;
                wr = W_hh[j * MEM_DIM + kk];
                wz = W_hh[(MEM_DIM + j) * MEM_DIM + kk];
            }
        }
        g_Wr[k * JPAD + j] = wr;
        g_Wz[k * JPAD + j] = wz;
        if (k < MSG_DIM)
            g_Wni[k * JPAD + j] = (j < MEM_DIM) ? W_ih[(2 * MEM_DIM + j) * MSG_DIM + k] : 0.f;
        if (k < MEM_DIM)
            g_Wnh[k * JPAD + j] = (j < MEM_DIM) ? W_hh[(2 * MEM_DIM + j) * MEM_DIM + k] : 0.f;
    }
    if (idx < JPAD) {
        int j = idx;
        float br = 0.f, bz = 0.f, bi = 0.f, bh = 0.f;
        if (j < MEM_DIM) {
            br = b_ih[j]               + b_hh[j];
            bz = b_ih[MEM_DIM + j]     + b_hh[MEM_DIM + j];
            bi = b_ih[2 * MEM_DIM + j];
            bh = b_hh[2 * MEM_DIM + j];
        }
        g_bias[j]            = br;
        g_bias[JPAD + j]     = bz;
        g_bias[2 * JPAD + j] = bi;
        g_bias[3 * JPAD + j] = bh;
    }
}

// ---------------------------------------------------------------------------
// Passthrough copy (vectorized) with scalar tail. Full occupancy, MLP-rich.
// ---------------------------------------------------------------------------
__global__ void copy_kernel(const float* __restrict__ src, float* __restrict__ dst, long long n) {
    long long i = (long long)blockIdx.x * blockDim.x + threadIdx.x;
    long long n4 = n >> 2;
    if (i < n4) {
        ((float4*)dst)[i] = ((const float4*)src)[i];
    }
    long long tail = n & 3;
    if (i < tail) {
        dst[n4 * 4 + i] = src[n4 * 4 + i];
    }
}

// ---------------------------------------------------------------------------
// Fused gather + GRU GEMM + elementwise + scatter.
// Block: 16 update rows. Thread j (<172) owns output column j across all 16
// rows, with 4 gate accumulators each, packed 2 rows per f32x2 register.
// ---------------------------------------------------------------------------
__global__ void __launch_bounds__(NTHREADS, 3)
gru_kernel(const int*   __restrict__ node_ids,
           const float* __restrict__ messages,
           const float* __restrict__ timestamps,
           const float* __restrict__ memory,
           float*       __restrict__ out,
           int n_upd, long long n_nodes)
{
    __shared__ __align__(16) float xT[KDIM][XSTRIDE];   // transposed [k][row]
    __shared__ int   s_nid[ROWS];
    __shared__ float s_ts [ROWS];

    const int tid  = threadIdx.x;
    const int row0 = blockIdx.x * ROWS;

    if (tid < ROWS) {
        int r = row0 + tid;
        if (r < n_upd) { s_nid[tid] = node_ids[r]; s_ts[tid] = timestamps[r]; }
        else           { s_nid[tid] = -1;          s_ts[tid] = 0.f; }
    }
    __syncthreads();

    // Gather x = [msg | h] transposed into smem. Coalesced global reads.
    for (int idx = tid; idx < ROWS * KDIM; idx += NTHREADS) {
        int r = idx / KDIM;
        int k = idx - r * KDIM;
        float v = 0.f;
        int nid = s_nid[r];
        if (nid >= 0) {
            v = (k < MSG_DIM)
              ? messages[(size_t)(row0 + r) * MSG_DIM + k]
              : memory  [(size_t)nid * MEM_DIM + (k - MSG_DIM)];
        }
        xT[k][r] = v;
    }
    __syncthreads();

    const int j = tid;
    if (j < MEM_DIM) {
        u64 ar2[ROWS / 2], az2[ROWS / 2], ani2[ROWS / 2], anh2[ROWS / 2];
        u64 z0 = dup2(0.f);
        #pragma unroll
        for (int p = 0; p < ROWS / 2; p++) { ar2[p] = z0; az2[p] = z0; ani2[p] = z0; anh2[p] = z0; }

        const float* __restrict__ pr = g_Wr  + j;
        const float* __restrict__ pz = g_Wz  + j;
        const float* __restrict__ pi = g_Wni + j;
        const float* __restrict__ ph = g_Wnh + j;

        // Phase 1: k in [0,100) -> gates r, z, i_n
        #pragma unroll 4
        for (int k = 0; k < MSG_DIM; k++) {
            u64 wr2 = dup2(pr[k * JPAD]);
            u64 wz2 = dup2(pz[k * JPAD]);
            u64 wi2 = dup2(pi[k * JPAD]);
            const ulonglong2* xq = (const ulonglong2*)&xT[k][0];
            #pragma unroll
            for (int q = 0; q < 4; q++) {
                ulonglong2 xv = xq[q];
                ar2 [2*q]   = fma2(wr2, xv.x, ar2 [2*q]);
                ar2 [2*q+1] = fma2(wr2, xv.y, ar2 [2*q+1]);
                az2 [2*q]   = fma2(wz2, xv.x, az2 [2*q]);
                az2 [2*q+1] = fma2(wz2, xv.y, az2 [2*q+1]);
                ani2[2*q]   = fma2(wi2, xv.x, ani2[2*q]);
                ani2[2*q+1] = fma2(wi2, xv.y, ani2[2*q+1]);
            }
        }
        // Phase 2: k in [100,272) -> gates r, z, h_n
        #pragma unroll 4
        for (int k = MSG_DIM; k < KDIM; k++) {
            u64 wr2 = dup2(pr[k * JPAD]);
            u64 wz2 = dup2(pz[k * JPAD]);
            u64 wh2 = dup2(ph[(k - MSG_DIM) * JPAD]);
            const ulonglong2* xq = (const ulonglong2*)&xT[k][0];
            #pragma unroll
            for (int q = 0; q < 4; q++) {
                ulonglong2 xv = xq[q];
                ar2 [2*q]   = fma2(wr2, xv.x, ar2 [2*q]);
                ar2 [2*q+1] = fma2(wr2, xv.y, ar2 [2*q+1]);
                az2 [2*q]   = fma2(wz2, xv.x, az2 [2*q]);
                az2 [2*q+1] = fma2(wz2, xv.y, az2 [2*q+1]);
                anh2[2*q]   = fma2(wh2, xv.x, anh2[2*q]);
                anh2[2*q+1] = fma2(wh2, xv.y, anh2[2*q+1]);
            }
        }

        const float br = g_bias[j];
        const float bz = g_bias[JPAD + j];
        const float bi = g_bias[2 * JPAD + j];
        const float bh = g_bias[3 * JPAD + j];

        #pragma unroll
        for (int p = 0; p < ROWS / 2; p++) {
            float2 arv = unpack2(ar2[p]);
            float2 azv = unpack2(az2[p]);
            float2 aiv = unpack2(ani2[p]);
            float2 ahv = unpack2(anh2[p]);
            #pragma unroll
            for (int s = 0; s < 2; s++) {
                int r = 2 * p + s;
                int nid = s_nid[r];
                if (nid < 0) continue;
                float a_r = (s ? arv.y : arv.x) + br;
                float a_z = (s ? azv.y : azv.x) + bz;
                float a_i = (s ? aiv.y : aiv.x) + bi;
                float a_h = (s ? ahv.y : ahv.x) + bh;
                float rg = 1.f / (1.f + expf(-a_r));
                float zg = 1.f / (1.f + expf(-a_z));
                float ng = tanhf(a_i + rg * a_h);
                float h_old = xT[MSG_DIM + j][r];
                out[(size_t)nid * MEM_DIM + j] = (1.f - zg) * ng + zg * h_old;
            }
        }
    }

    if (tid < ROWS && s_nid[tid] >= 0) {
        out[(size_t)n_nodes * MEM_DIM + s_nid[tid]] = s_ts[tid];
    }
}

// ---------------------------------------------------------------------------
extern "C" void kernel_launch(void* const* d_in, const int* in_sizes, int n_in,
                              void* d_out, int out_size) {
    const int*   node_ids    = (const int*)  d_in[0];
    const float* messages    = (const float*)d_in[1];
    const float* timestamps  = (const float*)d_in[2];
    const float* memory      = (const float*)d_in[3];
    const float* last_update = (const float*)d_in[4];
    const float* W_ih        = (const float*)d_in[5];
    const float* W_hh        = (const float*)d_in[6];
    const float* b_ih        = (const float*)d_in[7];
    const float* b_hh        = (const float*)d_in[8];
    float* out = (float*)d_out;

    const int       n_upd   = in_sizes[0];
    const long long n_nodes = in_sizes[4];
    const long long nmem    = n_nodes * (long long)MEM_DIM;

    // Repack weights (tiny)
    prep_kernel<<<(KDIM * JPAD + 255) / 256, 256>>>(W_ih, W_hh, b_ih, b_hh);

    // Passthrough copy: memory, then last_update
    {
        long long n4 = (nmem + 3) >> 2;
        copy_kernel<<<(unsigned)((n4 + 255) / 256), 256>>>(memory, out, nmem);
        long long n4b = (n_nodes + 3) >> 2;
        copy_kernel<<<(unsigned)((n4b + 255) / 256), 256>>>(last_update, out + nmem, n_nodes);
    }

    // Fused gather + GRU + scatter (after copy in-stream, so scatter wins)
    gru_kernel<<<(n_upd + ROWS - 1) / ROWS, NTHREADS>>>(
        node_ids, messages, timestamps, memory, out, n_upd, n_nodes);
}